// round 3
// baseline (speedup 1.0000x reference)
#include <cuda_runtime.h>

// Blur_80281528697499: depthwise UpFirDn2D(up=2, dn=2, 4x4 kernel) on
// x:(8,256,128,128) f32. Collapses analytically to a 2x2 stencil with the
// odd-tap filter coefficients f[1,1], f[1,3], f[3,1], f[3,3].
//
// Layout: B=8, C=256, H=128, W=128. 2048 planes of 128x128.
// One warp = one row (32 lanes x float4). 256 threads/block = 8 rows/block.
// 16 blocks per plane -> grid = 2048*16 = 32768 blocks.

#define NB 8
#define NC 256
#define NH 128
#define NW 128

__global__ void __launch_bounds__(256) blur2x2_kernel(
    const float* __restrict__ x,
    const float* __restrict__ filt,
    float* __restrict__ out)
{
    const int block_in_plane = blockIdx.x & 15;         // 16 blocks/plane
    const int plane          = blockIdx.x >> 4;          // b*C + c, 0..2047
    const int c              = plane & (NC - 1);

    // Per-channel filter taps (only odd-odd taps of the 4x4 contribute).
    const float* fp = filt + c * 16;
    const float wA = __ldg(fp + 5);    // f[1][1]
    const float wB = __ldg(fp + 7);    // f[1][3]
    const float wC = __ldg(fp + 13);   // f[3][1]
    const float wD = __ldg(fp + 15);   // f[3][3]

    const int off = block_in_plane * 256 + threadIdx.x;  // float4 index in plane
    const int y   = off >> 5;                            // row (warp-uniform)
    const int x4  = off & 31;                            // float4 column = lane

    const float4* row0 = reinterpret_cast<const float4*>(
        x + (size_t)plane * (NH * NW) + (size_t)y * NW);

    float4 a = row0[x4];
    float an = __shfl_down_sync(0xffffffffu, a.x, 1);
    if (x4 == 31) an = 0.0f;                             // right boundary -> 0

    float4 b;
    float  bn;
    if (y + 1 < NH) {                                    // warp-uniform branch
        float4 bb = row0[x4 + (NW / 4)];
        bn = __shfl_down_sync(0xffffffffu, bb.x, 1);
        if (x4 == 31) bn = 0.0f;
        b = bb;
    } else {                                             // bottom boundary -> 0
        b  = make_float4(0.0f, 0.0f, 0.0f, 0.0f);
        bn = 0.0f;
    }

    float4 o;
    o.x = wA * a.x + wB * a.y + wC * b.x + wD * b.y;
    o.y = wA * a.y + wB * a.z + wC * b.y + wD * b.z;
    o.z = wA * a.z + wB * a.w + wC * b.z + wD * b.w;
    o.w = wA * a.w + wB * an  + wC * b.w + wD * bn;

    reinterpret_cast<float4*>(out)[(size_t)plane * (NH * NW / 4) + off] = o;
}

extern "C" void kernel_launch(void* const* d_in, const int* in_sizes, int n_in,
                              void* d_out, int out_size)
{
    const float* x    = (const float*)d_in[0];   // (8,256,128,128) f32
    const float* filt = (const float*)d_in[1];   // (256,1,4,4) f32
    float* out = (float*)d_out;                  // (8,256,128,128) f32

    const int planes = NB * NC;                  // 2048
    const int blocks = planes * 16;              // 32768
    blur2x2_kernel<<<blocks, 256>>>(x, filt, out);
}

// round 4
// speedup vs baseline: 1.0654x; 1.0654x over previous
#include <cuda_runtime.h>

// Blur_80281528697499: depthwise UpFirDn2D(up=2, dn=2, 4x4) == 2x2 stencil
// with odd-odd filter taps. x:(8,256,128,128) f32 -> out same shape.
//
// Row-strip blocking: one warp = 4 output rows x 128 px (32 lanes x float4).
// Front-loads 5 input rows (MLP=5 independent 16B LDGs per thread), computes
// 4 outputs with register reuse (1.25 reads per output vs 2.0 before).
// Block = 8 warps = 32 rows; plane (128 rows) = 4 blocks; grid = 2048*4.

#define NB 8
#define NC 256
#define NH 128
#define NW 128
#define R  4   // output rows per warp

__global__ void __launch_bounds__(256) blur2x2_strip_kernel(
    const float* __restrict__ x,
    const float* __restrict__ filt,
    float* __restrict__ out)
{
    const int pblk  = blockIdx.x & 3;          // 4 blocks per plane
    const int plane = blockIdx.x >> 2;         // b*C + c, 0..2047
    const int c     = plane & (NC - 1);

    const int warp  = threadIdx.x >> 5;
    const int lane  = threadIdx.x & 31;
    const int y0    = pblk * 32 + warp * R;    // first output row of strip

    // Per-channel filter taps (only odd-odd taps of the 4x4 contribute).
    const float* fp = filt + c * 16;
    const float wA = __ldg(fp + 5);    // f[1][1]
    const float wB = __ldg(fp + 7);    // f[1][3]
    const float wC = __ldg(fp + 13);   // f[3][1]
    const float wD = __ldg(fp + 15);   // f[3][3]

    const float4* base = reinterpret_cast<const float4*>(
        x + (size_t)plane * (NH * NW));

    // Front-load R+1 = 5 rows (all independent -> 5 LDG.128 in flight).
    float4 r[R + 1];
    const bool last_strip = (y0 + R >= NH);    // warp-uniform
    #pragma unroll
    for (int i = 0; i < R; i++)
        r[i] = base[(y0 + i) * (NW / 4) + lane];
    if (!last_strip)
        r[R] = base[(y0 + R) * (NW / 4) + lane];
    else
        r[R] = make_float4(0.0f, 0.0f, 0.0f, 0.0f);

    // Next-lane .x for each row (right neighbor of the .w element).
    float n[R + 1];
    #pragma unroll
    for (int i = 0; i < R + 1; i++) {
        n[i] = __shfl_down_sync(0xffffffffu, r[i].x, 1);
        if (lane == 31) n[i] = 0.0f;           // right boundary -> 0
    }

    float4* obase = reinterpret_cast<float4*>(out) +
                    (size_t)plane * (NH * NW / 4);

    #pragma unroll
    for (int i = 0; i < R; i++) {
        const float4 a = r[i];
        const float4 b = r[i + 1];
        const float  an = n[i];
        const float  bn = n[i + 1];
        float4 o;
        o.x = wA * a.x + wB * a.y + wC * b.x + wD * b.y;
        o.y = wA * a.y + wB * a.z + wC * b.y + wD * b.z;
        o.z = wA * a.z + wB * a.w + wC * b.z + wD * b.w;
        o.w = wA * a.w + wB * an  + wC * b.w + wD * bn;
        obase[(y0 + i) * (NW / 4) + lane] = o;
    }
}

extern "C" void kernel_launch(void* const* d_in, const int* in_sizes, int n_in,
                              void* d_out, int out_size)
{
    const float* x    = (const float*)d_in[0];   // (8,256,128,128) f32
    const float* filt = (const float*)d_in[1];   // (256,1,4,4) f32
    float* out = (float*)d_out;                  // (8,256,128,128) f32

    const int planes = NB * NC;                  // 2048
    const int blocks = planes * 4;               // 8192
    blur2x2_strip_kernel<<<blocks, 256>>>(x, filt, out);
}